// round 13
// baseline (speedup 1.0000x reference)
#include <cuda_runtime.h>

#define BATCH 8
#define M 4096
#define NPTS 4096
#define NSLICES 4
#define SLICE (NPTS / NSLICES)               // 1024 gt points per block
#define ROWS_PB 32                           // rows per block (4 per warp)
#define RGROUPS (M / ROWS_PB)                // 128
#define NBLOCKS (BATCH * RGROUPS * NSLICES)  // 4096
#define NROWS (BATCH * M)                    // 32768

// Both clouds pre-scaled by C = 10*log2(e): chain gives u = C*d directly,
// e = exp2(-u) = exp(-d/0.1). Row result is (sum e*u / sum e) / C.
#define SCALE_C 14.4269504088896f
#define INV_C   (1.0f / SCALE_C)
// Bias (in u^2 units) so the fma-chain u^2 is provably >= 0; delta-d ~ 1e-4.
#define U2_BIAS 1e-2f

__device__ float g_s[NROWS * NSLICES];   // per-(row, slice) sum of e
__device__ float g_w[NROWS * NSLICES];   // per-(row, slice) sum of e*u
__device__ float g_p2[64];
__device__ int   g_ctr;                  // last-block counter (self-resetting)

__device__ __forceinline__ float sqrt_approx(float x) {
    float r; asm("sqrt.approx.f32 %0, %1;" : "=f"(r) : "f"(x)); return r;
}
// negation folds into the MUFU input modifier
__device__ __forceinline__ float ex2_neg(float x) {
    float r; asm("ex2.approx.f32 %0, %1;" : "=f"(r) : "f"(-x)); return r;
}

__global__ __launch_bounds__(256, 4)
void emd_main(const float* __restrict__ pred, const float* __restrict__ gt)
{
    // AoS: one float4 {Cx, Cy, Cz, |Cg|^2} per gt point
    __shared__ __align__(16) float4 sPt[SLICE];

    const int bid = blockIdx.x;
    const int sl  = bid & (NSLICES - 1);
    const int rg  = (bid >> 2) & (RGROUPS - 1);
    const int b   = bid >> 9;

    // Stage slice coalesced: thread t owns points 4t..4t+3 via 3x float4
    {
        const float4* g4 = (const float4*)(gt + ((size_t)b * NPTS + (size_t)sl * SLICE) * 3);
        const int t = threadIdx.x;
        const float4 v0 = g4[3 * t + 0];
        const float4 v1 = g4[3 * t + 1];
        const float4 v2 = g4[3 * t + 2];
        float px[4], py[4], pz[4];
        px[0] = v0.x; py[0] = v0.y; pz[0] = v0.z;
        px[1] = v0.w; py[1] = v1.x; pz[1] = v1.y;
        px[2] = v1.z; py[2] = v1.w; pz[2] = v2.x;
        px[3] = v2.y; py[3] = v2.z; pz[3] = v2.w;
#pragma unroll
        for (int k = 0; k < 4; k++) {
            float gx = SCALE_C * px[k];
            float gy = SCALE_C * py[k];
            float gz = SCALE_C * pz[k];
            float g2 = fmaf(gx, gx, fmaf(gy, gy, gz * gz));
            sPt[4 * t + k] = make_float4(gx, gy, gz, g2);
        }
    }
    __syncthreads();

    const int warp = threadIdx.x >> 5;
    const int lane = threadIdx.x & 31;
    const int m0   = rg * ROWS_PB + warp * 4;   // this warp's 4 rows

    // Per-row scalar constants (C-scaled): q = -2*C*p, p2 = |C*p|^2 + bias
    float qx[4], qy[4], qz[4], p2[4];
    const float* p = pred + ((size_t)b * M + m0) * 3;
#pragma unroll
    for (int r = 0; r < 4; r++) {
        float px = SCALE_C * __ldg(p + 3 * r + 0);
        float py = SCALE_C * __ldg(p + 3 * r + 1);
        float pz = SCALE_C * __ldg(p + 3 * r + 2);
        qx[r] = -2.0f * px;
        qy[r] = -2.0f * py;
        qz[r] = -2.0f * pz;
        p2[r] = fmaf(px, px, fmaf(py, py, pz * pz)) + U2_BIAS;
    }

    float sA[4] = {0.f, 0.f, 0.f, 0.f};
    float wA[4] = {0.f, 0.f, 0.f, 0.f};

    // Conflict-free mapping: lane L handles points {L+64j, L+32+64j}.
#pragma unroll
    for (int j = 0; j < 16; j++) {
        const int n = lane + 64 * j;
        const float4 P0 = sPt[n];
        const float4 P1 = sPt[n + 32];
#pragma unroll
        for (int r = 0; r < 4; r++) {
            float b0 = P0.w + p2[r];
            float b1 = P1.w + p2[r];
            float u20 = fmaf(qx[r], P0.x, fmaf(qy[r], P0.y, fmaf(qz[r], P0.z, b0)));
            float u21 = fmaf(qx[r], P1.x, fmaf(qy[r], P1.y, fmaf(qz[r], P1.z, b1)));
            float u0 = sqrt_approx(u20);        // u = C*d
            float u1 = sqrt_approx(u21);
            float e0 = ex2_neg(u0);             // exp(-d/0.1), underflow -> 0 ok
            float e1 = ex2_neg(u1);
            sA[r] += e0;
            wA[r] = fmaf(e0, u0, wA[r]);
            sA[r] += e1;
            wA[r] = fmaf(e1, u1, wA[r]);
        }
    }

    // Warp-reduce (s, w) per row; this warp owns (row, slice)
#pragma unroll
    for (int r = 0; r < 4; r++) {
        float s = sA[r], w = wA[r];
#pragma unroll
        for (int o = 16; o; o >>= 1) {
            s += __shfl_xor_sync(0xffffffffu, s, o);
            w += __shfl_xor_sync(0xffffffffu, w, o);
        }
        if (lane == 0) {
            const int row = b * M + m0 + r;
            g_s[row * NSLICES + sl] = s;
            g_w[row * NSLICES + sl] = w;
        }
    }
}

// Combine slices -> per-row w/s -> 64 block partials; the LAST block's
// thread 0 serially sums the partials (deterministic) and writes the scalar.
__global__ void emd_combine(float* __restrict__ out)
{
    __shared__ float sm[16];
    __shared__ int   last;
    const int row = blockIdx.x * 512 + threadIdx.x;   // 64 x 512 = 32768 rows
    float s = 0.0f, w = 0.0f;
#pragma unroll
    for (int k = 0; k < NSLICES; k++) {
        s += g_s[row * NSLICES + k];
        w += g_w[row * NSLICES + k];
    }
    float val = (w / s) * INV_C;          // per-row softmin-weighted distance
#pragma unroll
    for (int o = 16; o; o >>= 1)
        val += __shfl_xor_sync(0xffffffffu, val, o);
    if ((threadIdx.x & 31) == 0) sm[threadIdx.x >> 5] = val;
    __syncthreads();
    if (threadIdx.x < 16) {
        float v = sm[threadIdx.x];
#pragma unroll
        for (int o = 8; o; o >>= 1)
            v += __shfl_xor_sync(0xffffu, v, o);
        if (threadIdx.x == 0) g_p2[blockIdx.x] = v;
    }

    // Publish partial, then elect the last block. All threads reach the
    // barrier; only the last block's thread 0 does the (tiny) final sum.
    __threadfence();
    if (threadIdx.x == 0)
        last = (atomicAdd(&g_ctr, 1) == (int)gridDim.x - 1);
    __syncthreads();
    if (last && threadIdx.x == 0) {
        __threadfence();                  // all g_p2 writes visible
        float acc = 0.0f;
#pragma unroll
        for (int i = 0; i < 64; i++)      // independent loads -> full MLP
            acc += g_p2[i];
        out[0] = acc * (1.0f / (float)NROWS);   // LOSS_WEIGHT = 1.0
        g_ctr = 0;                        // self-reset for graph replay
    }
}

extern "C" void kernel_launch(void* const* d_in, const int* in_sizes, int n_in,
                              void* d_out, int out_size)
{
    const float* pred = (const float*)d_in[0];  // [B, M, 3] fp32
    const float* gt   = (const float*)d_in[1];  // [B, N, 3] fp32
    float* out        = (float*)d_out;          // scalar fp32

    emd_main<<<NBLOCKS, 256>>>(pred, gt);
    emd_combine<<<64, 512>>>(out);
}

// round 14
// speedup vs baseline: 1.0899x; 1.0899x over previous
#include <cuda_runtime.h>
#include <cuda_fp16.h>
#include <cstring>

#define BATCH 8
#define M 4096
#define NPTS 4096
#define NSLICES 4
#define SLICE (NPTS / NSLICES)               // 1024 gt points per block
#define ROWS_PB 32                           // rows per block (4 per warp)
#define RGROUPS (M / ROWS_PB)                // 128
#define NBLOCKS (BATCH * RGROUPS * NSLICES)  // 4096
#define NROWS (BATCH * M)                    // 32768

// f16-exact scale: round_to_f16(10*log2(e)) = 14.4296875.
// ex2 arg: 12 - C*d  =>  e = 2^12 * softmin weight; the 2^12 cancels in w/s.
#define C_F16 14.4296875f
// Bias folded into p2 so the fma-chain d^2 is provably >= 0.
#define D2_BIAS 2e-5f

__device__ float g_s[NROWS * NSLICES];   // per-(row, slice) sum of e
__device__ float g_w[NROWS * NSLICES];   // per-(row, slice) sum of e*d
__device__ float g_p2[64];

// Fused tail: two scalar f32 d^2 (>=0 by construction) -> sqrt x2 (MUFU) ->
// f16x2 pack -> arg = 12 - C*d -> ex2.f16x2 (ONE MUFU pass) -> s += e, w += e*d.
__device__ __forceinline__ void tail(float d2lo, float d2hi,
                                     unsigned hC, unsigned hB,
                                     unsigned& s, unsigned& w) {
    asm("{\n\t"
        ".reg .f32 slo, shi;\n\t"
        ".reg .b32 hd, arg, e;\n\t"
        "sqrt.approx.f32 slo, %2;\n\t"
        "sqrt.approx.f32 shi, %3;\n\t"
        "cvt.rn.f16x2.f32 hd, shi, slo;\n\t"
        "fma.rn.f16x2 arg, hd, %4, %5;\n\t"
        "ex2.approx.f16x2 e, arg;\n\t"
        "add.rn.f16x2 %0, %0, e;\n\t"
        "fma.rn.f16x2 %1, e, hd, %1;\n\t"
        "}"
        : "+r"(s), "+r"(w)
        : "f"(d2lo), "f"(d2hi), "r"(hC), "r"(hB));
}

__device__ __forceinline__ void flush_h2(unsigned& h, float& f) {
    __half2 v; memcpy(&v, &h, 4);
    f += __low2float(v) + __high2float(v);
    h = 0u;
}

__global__ __launch_bounds__(256, 6)
void emd_main(const float* __restrict__ pred, const float* __restrict__ gt)
{
    // AoS: one float4 {x, y, z, |g|^2} per gt point
    __shared__ __align__(16) float4 sPt[SLICE];

    const int bid = blockIdx.x;
    const int sl  = bid & (NSLICES - 1);
    const int rg  = (bid >> 2) & (RGROUPS - 1);
    const int b   = bid >> 9;

    // Stage slice coalesced: thread t owns points 4t..4t+3 via 3x float4
    {
        const float4* g4 = (const float4*)(gt + ((size_t)b * NPTS + (size_t)sl * SLICE) * 3);
        const int t = threadIdx.x;
        const float4 v0 = g4[3 * t + 0];
        const float4 v1 = g4[3 * t + 1];
        const float4 v2 = g4[3 * t + 2];
        float px[4], py[4], pz[4];
        px[0] = v0.x; py[0] = v0.y; pz[0] = v0.z;
        px[1] = v0.w; py[1] = v1.x; pz[1] = v1.y;
        px[2] = v1.z; py[2] = v1.w; pz[2] = v2.x;
        px[3] = v2.y; py[3] = v2.z; pz[3] = v2.w;
#pragma unroll
        for (int k = 0; k < 4; k++) {
            float g2 = fmaf(px[k], px[k], fmaf(py[k], py[k], pz[k] * pz[k]));
            sPt[4 * t + k] = make_float4(px[k], py[k], pz[k], g2);
        }
    }
    __syncthreads();

    const int warp = threadIdx.x >> 5;
    const int lane = threadIdx.x & 31;
    const int m0   = rg * ROWS_PB + warp * 4;   // this warp's 4 rows

    // Per-row scalar constants: q = -2p, p2 = |p|^2 + bias
    float qx[4], qy[4], qz[4], p2[4];
    const float* p = pred + ((size_t)b * M + m0) * 3;
#pragma unroll
    for (int r = 0; r < 4; r++) {
        float px = __ldg(p + 3 * r + 0);
        float py = __ldg(p + 3 * r + 1);
        float pz = __ldg(p + 3 * r + 2);
        qx[r] = -2.0f * px;
        qy[r] = -2.0f * py;
        qz[r] = -2.0f * pz;
        p2[r] = fmaf(px, px, fmaf(py, py, pz * pz)) + D2_BIAS;
    }

    unsigned hC, hB;
    { __half2 t = __float2half2_rn(-C_F16); memcpy(&hC, &t, 4); }
    { __half2 t = __float2half2_rn(12.0f);  memcpy(&hB, &t, 4); }

    unsigned sh[4] = {0u, 0u, 0u, 0u};
    unsigned wh[4] = {0u, 0u, 0u, 0u};
    float sF[4] = {0.f, 0.f, 0.f, 0.f};
    float wF[4] = {0.f, 0.f, 0.f, 0.f};

    // Conflict-free mapping: lane L handles points {L+64j, L+32+64j}.
#pragma unroll
    for (int j = 0; j < 16; j++) {
        const int n = lane + 64 * j;
        const float4 P0 = sPt[n];
        const float4 P1 = sPt[n + 32];
#pragma unroll
        for (int r = 0; r < 4; r++) {
            float blo = P0.w + p2[r];
            float bhi = P1.w + p2[r];
            float d2lo = fmaf(qx[r], P0.x, fmaf(qy[r], P0.y, fmaf(qz[r], P0.z, blo)));
            float d2hi = fmaf(qx[r], P1.x, fmaf(qy[r], P1.y, fmaf(qz[r], P1.z, bhi)));
            tail(d2lo, d2hi, hC, hB, sh[r], wh[r]);
        }
        if (j == 7) {                 // single mid flush: <=8 f16 terms/half
#pragma unroll
            for (int r = 0; r < 4; r++) {
                flush_h2(sh[r], sF[r]);
                flush_h2(wh[r], wF[r]);
            }
        }
    }
#pragma unroll
    for (int r = 0; r < 4; r++) {
        flush_h2(sh[r], sF[r]);
        flush_h2(wh[r], wF[r]);
    }

    // Warp-reduce (s, w) per row; this warp owns (row, slice)
#pragma unroll
    for (int r = 0; r < 4; r++) {
        float s = sF[r], w = wF[r];
#pragma unroll
        for (int o = 16; o; o >>= 1) {
            s += __shfl_xor_sync(0xffffffffu, s, o);
            w += __shfl_xor_sync(0xffffffffu, w, o);
        }
        if (lane == 0) {
            const int row = b * M + m0 + r;
            g_s[row * NSLICES + sl] = s;
            g_w[row * NSLICES + sl] = w;
        }
    }
}

__global__ void emd_combine(void)
{
    __shared__ float sm[16];
    const int row = blockIdx.x * 512 + threadIdx.x;   // 64 x 512 = 32768 rows
    float s = 0.0f, w = 0.0f;
#pragma unroll
    for (int k = 0; k < NSLICES; k++) {
        s += g_s[row * NSLICES + k];
        w += g_w[row * NSLICES + k];
    }
    float val = w / s;                    // per-row softmin-weighted distance
#pragma unroll
    for (int o = 16; o; o >>= 1)
        val += __shfl_xor_sync(0xffffffffu, val, o);
    if ((threadIdx.x & 31) == 0) sm[threadIdx.x >> 5] = val;
    __syncthreads();
    if (threadIdx.x < 16) {
        float v = sm[threadIdx.x];
#pragma unroll
        for (int o = 8; o; o >>= 1)
            v += __shfl_xor_sync(0xffffu, v, o);
        if (threadIdx.x == 0) g_p2[blockIdx.x] = v;
    }
}

__global__ void emd_final(float* __restrict__ out)
{
    __shared__ float sm[2];
    float v = g_p2[threadIdx.x];          // 64 threads
#pragma unroll
    for (int o = 16; o; o >>= 1)
        v += __shfl_xor_sync(0xffffffffu, v, o);
    if ((threadIdx.x & 31) == 0) sm[threadIdx.x >> 5] = v;
    __syncthreads();
    if (threadIdx.x == 0)
        out[0] = (sm[0] + sm[1]) * (1.0f / (float)NROWS);   // LOSS_WEIGHT = 1.0
}

extern "C" void kernel_launch(void* const* d_in, const int* in_sizes, int n_in,
                              void* d_out, int out_size)
{
    const float* pred = (const float*)d_in[0];  // [B, M, 3] fp32
    const float* gt   = (const float*)d_in[1];  // [B, N, 3] fp32
    float* out        = (float*)d_out;          // scalar fp32

    emd_main<<<NBLOCKS, 256>>>(pred, gt);
    emd_combine<<<64, 512>>>();
    emd_final<<<1, 64>>>(out);
}

// round 15
// speedup vs baseline: 1.1710x; 1.0744x over previous
#include <cuda_runtime.h>
#include <cuda_fp16.h>
#include <cstring>

#define BATCH 8
#define M 4096
#define NPTS 4096
#define NSLICES 4
#define SLICE (NPTS / NSLICES)               // 1024 gt points per block
#define ROWS_PB 32                           // rows per block (4 per warp)
#define RGROUPS (M / ROWS_PB)                // 128
#define NBLOCKS (BATCH * RGROUPS * NSLICES)  // 4096
#define NROWS (BATCH * M)                    // 32768

// f16-exact scale: round_to_f16(10*log2(e)) = 14.4296875.
// ex2 arg: 12 - C*d  =>  e = 2^12 * softmin weight; the 2^12 cancels in w/s.
#define C_F16 14.4296875f
// Bias folded into p2 so the fma-chain d^2 is provably >= 0.
#define D2_BIAS 2e-5f

__device__ float g_s[NROWS * NSLICES];   // per-(row, slice) sum of e
__device__ float g_w[NROWS * NSLICES];   // per-(row, slice) sum of e*d
__device__ float g_p2[64];

// Fused tail: two scalar f32 d^2 (>=0 by construction) -> sqrt x2 (MUFU) ->
// f16x2 pack -> arg = 12 - C*d -> ex2.f16x2 (ONE MUFU pass) -> s += e, w += e*d.
__device__ __forceinline__ void tail(float d2lo, float d2hi,
                                     unsigned hC, unsigned hB,
                                     unsigned& s, unsigned& w) {
    asm("{\n\t"
        ".reg .f32 slo, shi;\n\t"
        ".reg .b32 hd, arg, e;\n\t"
        "sqrt.approx.f32 slo, %2;\n\t"
        "sqrt.approx.f32 shi, %3;\n\t"
        "cvt.rn.f16x2.f32 hd, shi, slo;\n\t"
        "fma.rn.f16x2 arg, hd, %4, %5;\n\t"
        "ex2.approx.f16x2 e, arg;\n\t"
        "add.rn.f16x2 %0, %0, e;\n\t"
        "fma.rn.f16x2 %1, e, hd, %1;\n\t"
        "}"
        : "+r"(s), "+r"(w)
        : "f"(d2lo), "f"(d2hi), "r"(hC), "r"(hB));
}

__device__ __forceinline__ void flush_h2(unsigned& h, float& f) {
    __half2 v; memcpy(&v, &h, 4);
    f += __low2float(v) + __high2float(v);
    h = 0u;
}

__global__ __launch_bounds__(256, 5)
void emd_main(const float* __restrict__ pred, const float* __restrict__ gt)
{
    // AoS: one float4 {x, y, z, |g|^2} per gt point
    __shared__ __align__(16) float4 sPt[SLICE];

    const int bid = blockIdx.x;
    const int sl  = bid & (NSLICES - 1);
    const int rg  = (bid >> 2) & (RGROUPS - 1);
    const int b   = bid >> 9;

    // Stage slice coalesced: thread t owns points 4t..4t+3 via 3x float4
    {
        const float4* g4 = (const float4*)(gt + ((size_t)b * NPTS + (size_t)sl * SLICE) * 3);
        const int t = threadIdx.x;
        const float4 v0 = g4[3 * t + 0];
        const float4 v1 = g4[3 * t + 1];
        const float4 v2 = g4[3 * t + 2];
        float px[4], py[4], pz[4];
        px[0] = v0.x; py[0] = v0.y; pz[0] = v0.z;
        px[1] = v0.w; py[1] = v1.x; pz[1] = v1.y;
        px[2] = v1.z; py[2] = v1.w; pz[2] = v2.x;
        px[3] = v2.y; py[3] = v2.z; pz[3] = v2.w;
#pragma unroll
        for (int k = 0; k < 4; k++) {
            float g2 = fmaf(px[k], px[k], fmaf(py[k], py[k], pz[k] * pz[k]));
            sPt[4 * t + k] = make_float4(px[k], py[k], pz[k], g2);
        }
    }
    __syncthreads();

    const int warp = threadIdx.x >> 5;
    const int lane = threadIdx.x & 31;
    const int m0   = rg * ROWS_PB + warp * 4;   // this warp's 4 rows

    // Per-row scalar constants: q = -2p, p2 = |p|^2 + bias
    float qx[4], qy[4], qz[4], p2[4];
    const float* p = pred + ((size_t)b * M + m0) * 3;
#pragma unroll
    for (int r = 0; r < 4; r++) {
        float px = __ldg(p + 3 * r + 0);
        float py = __ldg(p + 3 * r + 1);
        float pz = __ldg(p + 3 * r + 2);
        qx[r] = -2.0f * px;
        qy[r] = -2.0f * py;
        qz[r] = -2.0f * pz;
        p2[r] = fmaf(px, px, fmaf(py, py, pz * pz)) + D2_BIAS;
    }

    unsigned hC, hB;
    { __half2 t = __float2half2_rn(-C_F16); memcpy(&hC, &t, 4); }
    { __half2 t = __float2half2_rn(12.0f);  memcpy(&hB, &t, 4); }

    unsigned sh[4] = {0u, 0u, 0u, 0u};
    unsigned wh[4] = {0u, 0u, 0u, 0u};
    float sF[4] = {0.f, 0.f, 0.f, 0.f};
    float wF[4] = {0.f, 0.f, 0.f, 0.f};

    // Conflict-free mapping: lane L handles points {L+64j, L+32+64j}.
#pragma unroll
    for (int j = 0; j < 16; j++) {
        const int n = lane + 64 * j;
        const float4 P0 = sPt[n];
        const float4 P1 = sPt[n + 32];
#pragma unroll
        for (int r = 0; r < 4; r++) {
            float blo = P0.w + p2[r];
            float bhi = P1.w + p2[r];
            float d2lo = fmaf(qx[r], P0.x, fmaf(qy[r], P0.y, fmaf(qz[r], P0.z, blo)));
            float d2hi = fmaf(qx[r], P1.x, fmaf(qy[r], P1.y, fmaf(qz[r], P1.z, bhi)));
            tail(d2lo, d2hi, hC, hB, sh[r], wh[r]);
        }
        if (j == 7) {                 // single mid flush: <=8 f16 terms/half
#pragma unroll
            for (int r = 0; r < 4; r++) {
                flush_h2(sh[r], sF[r]);
                flush_h2(wh[r], wF[r]);
            }
        }
    }
#pragma unroll
    for (int r = 0; r < 4; r++) {
        flush_h2(sh[r], sF[r]);
        flush_h2(wh[r], wF[r]);
    }

    // Warp-reduce (s, w) per row; this warp owns (row, slice)
#pragma unroll
    for (int r = 0; r < 4; r++) {
        float s = sF[r], w = wF[r];
#pragma unroll
        for (int o = 16; o; o >>= 1) {
            s += __shfl_xor_sync(0xffffffffu, s, o);
            w += __shfl_xor_sync(0xffffffffu, w, o);
        }
        if (lane == 0) {
            const int row = b * M + m0 + r;
            g_s[row * NSLICES + sl] = s;
            g_w[row * NSLICES + sl] = w;
        }
    }
}

__global__ void emd_combine(void)
{
    __shared__ float sm[16];
    const int row = blockIdx.x * 512 + threadIdx.x;   // 64 x 512 = 32768 rows
    float s = 0.0f, w = 0.0f;
#pragma unroll
    for (int k = 0; k < NSLICES; k++) {
        s += g_s[row * NSLICES + k];
        w += g_w[row * NSLICES + k];
    }
    float val = w / s;                    // per-row softmin-weighted distance
#pragma unroll
    for (int o = 16; o; o >>= 1)
        val += __shfl_xor_sync(0xffffffffu, val, o);
    if ((threadIdx.x & 31) == 0) sm[threadIdx.x >> 5] = val;
    __syncthreads();
    if (threadIdx.x < 16) {
        float v = sm[threadIdx.x];
#pragma unroll
        for (int o = 8; o; o >>= 1)
            v += __shfl_xor_sync(0xffffu, v, o);
        if (threadIdx.x == 0) g_p2[blockIdx.x] = v;
    }
}

__global__ void emd_final(float* __restrict__ out)
{
    __shared__ float sm[2];
    float v = g_p2[threadIdx.x];          // 64 threads
#pragma unroll
    for (int o = 16; o; o >>= 1)
        v += __shfl_xor_sync(0xffffffffu, v, o);
    if ((threadIdx.x & 31) == 0) sm[threadIdx.x >> 5] = v;
    __syncthreads();
    if (threadIdx.x == 0)
        out[0] = (sm[0] + sm[1]) * (1.0f / (float)NROWS);   // LOSS_WEIGHT = 1.0
}

extern "C" void kernel_launch(void* const* d_in, const int* in_sizes, int n_in,
                              void* d_out, int out_size)
{
    const float* pred = (const float*)d_in[0];  // [B, M, 3] fp32
    const float* gt   = (const float*)d_in[1];  // [B, N, 3] fp32
    float* out        = (float*)d_out;          // scalar fp32

    emd_main<<<NBLOCKS, 256>>>(pred, gt);
    emd_combine<<<64, 512>>>();
    emd_final<<<1, 64>>>(out);
}

// round 16
// speedup vs baseline: 1.2443x; 1.0625x over previous
#include <cuda_runtime.h>
#include <cuda_fp16.h>
#include <cstring>

#define BATCH 8
#define M 4096
#define NPTS 4096
#define NSLICES 4
#define SLICE (NPTS / NSLICES)               // 1024 gt points per block
#define ROWS_PB 32                           // rows per block (4 per warp)
#define RGROUPS (M / ROWS_PB)                // 128
#define NBLOCKS (BATCH * RGROUPS * NSLICES)  // 4096
#define NROWS (BATCH * M)                    // 32768

// f16-exact scale: round_to_f16(10*log2(e)) = 14.4296875.
// ex2 arg: 12 - C*d  =>  e = 2^12 * softmin weight; the 2^12 cancels in w/s.
#define C_F16 14.4296875f
// Bias folded into p2 so the fma-chain d^2 is provably >= 0.
#define D2_BIAS 2e-5f

__device__ float g_s[NROWS * NSLICES];   // per-(row, slice) sum of e
__device__ float g_w[NROWS * NSLICES];   // per-(row, slice) sum of e*d
__device__ float g_p2[128];

typedef unsigned long long ull;

__device__ __forceinline__ ull pack2(float lo, float hi) {
    ull r; asm("mov.b64 %0, {%1, %2};" : "=l"(r) : "f"(lo), "f"(hi)); return r;
}
// fma.rn.f32x2 -> FFMA2 (single SASS op, rt_SMSP=2 for two f32 lanes)
__device__ __forceinline__ ull fma2(ull a, ull b, ull c) {
    ull r; asm("fma.rn.f32x2 %0, %1, %2, %3;" : "=l"(r) : "l"(a), "l"(b), "l"(c)); return r;
}

// Tail: packed f32x2 d^2 (>=0 by construction) -> 2x sqrt (MUFU) -> f16x2
// pack -> arg = 12 - C*d -> ex2.f16x2 (MUFU) -> s += e, w += e*d (f16x2).
__device__ __forceinline__ void tailp(ull t, unsigned hC, unsigned hB,
                                      unsigned& s, unsigned& w) {
    asm("{\n\t"
        ".reg .f32 lo, hi, slo, shi;\n\t"
        ".reg .b32 hd, arg, e;\n\t"
        "mov.b64 {lo, hi}, %2;\n\t"
        "sqrt.approx.f32 slo, lo;\n\t"
        "sqrt.approx.f32 shi, hi;\n\t"
        "cvt.rn.f16x2.f32 hd, shi, slo;\n\t"
        "fma.rn.f16x2 arg, hd, %3, %4;\n\t"
        "ex2.approx.f16x2 e, arg;\n\t"
        "add.rn.f16x2 %0, %0, e;\n\t"
        "fma.rn.f16x2 %1, e, hd, %1;\n\t"
        "}"
        : "+r"(s), "+r"(w)
        : "l"(t), "r"(hC), "r"(hB));
}

__device__ __forceinline__ void flush_h2(unsigned& h, float& f) {
    __half2 v; memcpy(&v, &h, 4);
    f += __low2float(v) + __high2float(v);
    h = 0u;
}

__global__ __launch_bounds__(256, 4)
void emd_main(const float* __restrict__ pred, const float* __restrict__ gt)
{
    // SoA: float2-pair loads come out as natively paired f32x2 registers
    __shared__ __align__(16) float spx[SLICE];
    __shared__ __align__(16) float spy[SLICE];
    __shared__ __align__(16) float spz[SLICE];
    __shared__ __align__(16) float sg2[SLICE];

    const int bid = blockIdx.x;
    const int sl  = bid & (NSLICES - 1);
    const int rg  = (bid >> 2) & (RGROUPS - 1);
    const int b   = bid >> 9;

    // Stage slice coalesced: thread t owns points 4t..4t+3 via 3x float4
    {
        const float4* g4 = (const float4*)(gt + ((size_t)b * NPTS + (size_t)sl * SLICE) * 3);
        const int t = threadIdx.x;
        const float4 v0 = g4[3 * t + 0];
        const float4 v1 = g4[3 * t + 1];
        const float4 v2 = g4[3 * t + 2];
        float px[4], py[4], pz[4];
        px[0] = v0.x; py[0] = v0.y; pz[0] = v0.z;
        px[1] = v0.w; py[1] = v1.x; pz[1] = v1.y;
        px[2] = v1.z; py[2] = v1.w; pz[2] = v2.x;
        px[3] = v2.y; py[3] = v2.z; pz[3] = v2.w;
#pragma unroll
        for (int k = 0; k < 4; k++) {
            spx[4 * t + k] = px[k];
            spy[4 * t + k] = py[k];
            spz[4 * t + k] = pz[k];
            sg2[4 * t + k] = fmaf(px[k], px[k], fmaf(py[k], py[k], pz[k] * pz[k]));
        }
    }
    __syncthreads();

    const int warp = threadIdx.x >> 5;
    const int lane = threadIdx.x & 31;
    const int m0   = rg * ROWS_PB + warp * 4;   // this warp's 4 rows

    // Per-row packed-duplicated constants: {q,q}, {p2+bias, p2+bias}
    ull qx2[4], qy2[4], qz2[4], p22[4];
    const float* p = pred + ((size_t)b * M + m0) * 3;
#pragma unroll
    for (int r = 0; r < 4; r++) {
        float px = __ldg(p + 3 * r + 0);
        float py = __ldg(p + 3 * r + 1);
        float pz = __ldg(p + 3 * r + 2);
        qx2[r] = pack2(-2.0f * px, -2.0f * px);
        qy2[r] = pack2(-2.0f * py, -2.0f * py);
        qz2[r] = pack2(-2.0f * pz, -2.0f * pz);
        float pp = fmaf(px, px, fmaf(py, py, pz * pz)) + D2_BIAS;
        p22[r] = pack2(pp, pp);
    }
    const ull ONE2 = pack2(1.0f, 1.0f);

    unsigned hC, hB;
    { __half2 t = __float2half2_rn(-C_F16); memcpy(&hC, &t, 4); }
    { __half2 t = __float2half2_rn(12.0f);  memcpy(&hB, &t, 4); }

    unsigned sh[4] = {0u, 0u, 0u, 0u};
    unsigned wh[4] = {0u, 0u, 0u, 0u};
    float sF[4] = {0.f, 0.f, 0.f, 0.f};
    float wF[4] = {0.f, 0.f, 0.f, 0.f};

    // Lane L handles point pair {2L+64j, 2L+64j+1}; LDS.64 conflict-free.
    // Distance chain = 4x FFMA2 per (pair, row); tail = 2 sqrt + 1 ex2.f16x2.
#pragma unroll
    for (int j = 0; j < 16; j++) {
        const int n = 2 * lane + 64 * j;
        const ull xx = *(const ull*)&spx[n];
        const ull yy = *(const ull*)&spy[n];
        const ull zz = *(const ull*)&spz[n];
        const ull gg = *(const ull*)&sg2[n];
#pragma unroll
        for (int r = 0; r < 4; r++) {
            ull t = fma2(ONE2, gg, p22[r]);       // g2 + p2  (FFMA2)
            t = fma2(qz2[r], zz, t);
            t = fma2(qy2[r], yy, t);
            t = fma2(qx2[r], xx, t);              // packed d^2 for 2 points
            tailp(t, hC, hB, sh[r], wh[r]);
        }
        if (j == 7) {                 // single mid flush: <=8 f16 terms/half
#pragma unroll
            for (int r = 0; r < 4; r++) {
                flush_h2(sh[r], sF[r]);
                flush_h2(wh[r], wF[r]);
            }
        }
    }
#pragma unroll
    for (int r = 0; r < 4; r++) {
        flush_h2(sh[r], sF[r]);
        flush_h2(wh[r], wF[r]);
    }

    // Warp-reduce (s, w) per row; this warp owns (row, slice)
#pragma unroll
    for (int r = 0; r < 4; r++) {
        float s = sF[r], w = wF[r];
#pragma unroll
        for (int o = 16; o; o >>= 1) {
            s += __shfl_xor_sync(0xffffffffu, s, o);
            w += __shfl_xor_sync(0xffffffffu, w, o);
        }
        if (lane == 0) {
            const int row = b * M + m0 + r;
            g_s[row * NSLICES + sl] = s;
            g_w[row * NSLICES + sl] = w;
        }
    }
}

__global__ void emd_combine(void)
{
    __shared__ float sm[8];
    const int row = blockIdx.x * 256 + threadIdx.x;   // 128 x 256 = 32768 rows
    float s = 0.0f, w = 0.0f;
#pragma unroll
    for (int k = 0; k < NSLICES; k++) {
        s += g_s[row * NSLICES + k];
        w += g_w[row * NSLICES + k];
    }
    float val = w / s;                    // per-row softmin-weighted distance
#pragma unroll
    for (int o = 16; o; o >>= 1)
        val += __shfl_xor_sync(0xffffffffu, val, o);
    if ((threadIdx.x & 31) == 0) sm[threadIdx.x >> 5] = val;
    __syncthreads();
    if (threadIdx.x < 8) {
        float v = sm[threadIdx.x];
#pragma unroll
        for (int o = 4; o; o >>= 1)
            v += __shfl_xor_sync(0xffu, v, o);
        if (threadIdx.x == 0) g_p2[blockIdx.x] = v;
    }
}

__global__ void emd_final(float* __restrict__ out)
{
    __shared__ float sm[4];
    float v = g_p2[threadIdx.x];          // 128 threads
#pragma unroll
    for (int o = 16; o; o >>= 1)
        v += __shfl_xor_sync(0xffffffffu, v, o);
    if ((threadIdx.x & 31) == 0) sm[threadIdx.x >> 5] = v;
    __syncthreads();
    if (threadIdx.x == 0)
        out[0] = (sm[0] + sm[1] + sm[2] + sm[3]) * (1.0f / (float)NROWS);
}

extern "C" void kernel_launch(void* const* d_in, const int* in_sizes, int n_in,
                              void* d_out, int out_size)
{
    const float* pred = (const float*)d_in[0];  // [B, M, 3] fp32
    const float* gt   = (const float*)d_in[1];  // [B, N, 3] fp32
    float* out        = (float*)d_out;          // scalar fp32

    emd_main<<<NBLOCKS, 256>>>(pred, gt);
    emd_combine<<<128, 256>>>();
    emd_final<<<1, 128>>>(out);
}